// round 13
// baseline (speedup 1.0000x reference)
#include <cuda_runtime.h>
#include <cuda_bf16.h>
#include <cstdint>

#define NN 256
#define FF 16
#define HH 2048
#define PP 16
#define EE 32768

// Scratch (device globals; allocation is forbidden).
// Zero at module load; every launch restores them to zero after use, so no
// init kernel is needed (self-restoring invariant across graph replays).
__device__ int4 d_A4[NN * NN / 4];    // edge-count matrix (NO self-loops), 256 KB
__device__ int  d_deg[NN];            // edge in-degree (NO self-loop)
__device__ int  d_rowctr[NN];         // per-row consumption counters
__device__ int  d_degctr;             // global deg consumption counter

// ---------------------------------------------------------------------------
// K1: one edge per thread; spread global atomics onto zeroed A/deg.
// Block 0 also initializes q = bq for K2's atomic epilogue.
// Edge dtype probed at runtime (harness delivers int64 cast to int32).
// ---------------------------------------------------------------------------
__global__ __launch_bounds__(256) void k_edges(const void* __restrict__ ei_raw,
                                               const float* __restrict__ bq,
                                               float* __restrict__ q) {
    int t = threadIdx.x;
    if (blockIdx.x == 0) {            // q = bq (1024 float4)
        const float4* b4 = reinterpret_cast<const float4*>(bq);
        float4* q4 = reinterpret_cast<float4*>(q);
#pragma unroll
        for (int i = 0; i < 4; i++) q4[t + i * 256] = b4[t + i * 256];
    }

    const int*       e32 = (const int*)ei_raw;
    const long long* e64 = (const long long*)ei_raw;

    int probe = 0;
#pragma unroll
    for (int k = 0; k < 16; k++) probe |= e32[2 * k + 1];
    const bool is64 = (probe == 0);

    int e = blockIdx.x * 256 + t;     // 128 blocks -> e in [0, EE)
    int src, dst;
    if (is64) { src = (int)e64[e]; dst = (int)e64[EE + e]; }
    else      { src = e32[e];      dst = e32[EE + e];      }

    if ((unsigned)src < (unsigned)NN && (unsigned)dst < (unsigned)NN) {
        int* A = reinterpret_cast<int*>(d_A4);
        atomicAdd(&A[dst * NN + src], 1);
        atomicAdd(&d_deg[dst], 1);
    }
}

// ---------------------------------------------------------------------------
// K2 (mega): block (n, half). Wq loads (the only DRAM-sized traffic) are
// issued FIRST into registers; the prologue (agg + out half-row from
// L2-resident x/W) then executes under their latency.
//   dinv[s] = rsqrt(deg[s] + 1)                   (+1 = self-loop)
//   agg[f]  = dinv[n] * (sum_s A[n,s]*dinv[s]*x[s,f] + dinv[n]*x[n,f])
//   oh[hl]  = bias[h] + sum_f agg[f] * W[f,h],    h = half*1024 + hl
//   q[n,p] += sum_h oh[h] * Wq[n,h,p]             (atomic, 2 halves)
// After consuming A-row/deg, the last consumer zeroes them (self-restore).
// ---------------------------------------------------------------------------
__global__ __launch_bounds__(512) void k_mega(const float* __restrict__ x,
                                              const float* __restrict__ W,
                                              const float* __restrict__ bias,
                                              const float* __restrict__ Wq,
                                              float* __restrict__ q) {
    __shared__ float sdinv[NN];       // 1 KB
    __shared__ int   sArow[NN];       // 1 KB (A row n, edges only)
    __shared__ float spart[512];      // 2 KB (agg partials)
    __shared__ float sagg[FF];
    __shared__ float s_oh[1024];      // 4 KB (out half-row)
    __shared__ float sred[16 * PP];   // 1 KB
    __shared__ int   sflagA, sflagD;

    int n    = blockIdx.x >> 1;
    int half = blockIdx.x & 1;
    int t    = threadIdx.x;

    // === issue ALL Wq loads first: DRAM stream starts at block launch ===
    const float4* wq4 = reinterpret_cast<const float4*>(Wq)
                      + (size_t)n * (HH * PP / 4) + half * 4096;
    float4 v[8];
#pragma unroll
    for (int r = 0; r < 8; r++) v[r] = wq4[r * 512 + t];  // warp-contiguous

    // === prologue (runs under the Wq load latency) ===
    if (t < NN) sdinv[t] = rsqrtf((float)(d_deg[t] + 1));
    else if (t < NN + 64) reinterpret_cast<int4*>(sArow)[t - NN] = d_A4[n * 64 + (t - NN)];
    __syncthreads();

    // consumption bookkeeping (this block's A/deg reads are done)
    if (t == 0) sflagA = (atomicAdd(&d_rowctr[n], 1) == 1);       // 2nd of 2
    if (t == 1) sflagD = (atomicAdd(&d_degctr, 1) == 2 * NN - 1); // 512th of 512

    // agg partials straight from L2-hot x: thread (f=t&15, g=t>>4), 8 src each
    {
        int f = t & 15, g = t >> 4;
        float p = 0.0f;
#pragma unroll
        for (int k = 0; k < 8; k++) {
            int s = g * 8 + k;
            p += (float)sArow[s] * sdinv[s] * x[s * FF + f];
        }
        spart[t] = p;
    }
    __syncthreads();

    // self-restore scratch to zero (all readers provably done)
    if (sflagA) {
        if (t < 64) d_A4[n * 64 + t] = make_int4(0, 0, 0, 0);
        else if (t == 64) d_rowctr[n] = 0;
    }
    if (sflagD) {
        if (t < NN) d_deg[t] = 0;
        else if (t == NN) d_degctr = 0;
    }

    if (t < FF) {
        float a = sdinv[n] * x[n * FF + t];   // implicit self-loop (+1 diag)
#pragma unroll
        for (int g = 0; g < 32; g++) a += spart[g * FF + t];
        sagg[t] = a * sdinv[n];
    }
    __syncthreads();

    // out half-row: 1024 h, 2 per thread; W reads are L2 hits
#pragma unroll
    for (int i = 0; i < 2; i++) {
        int hl = t + i * 512;
        int h  = half * 1024 + hl;
        float val = bias[h];
#pragma unroll
        for (int f = 0; f < FF; f++) val = fmaf(sagg[f], W[f * HH + h], val);
        s_oh[hl] = val;
    }
    __syncthreads();

    // === consume prefetched Wq (idx -> h = idx>>2, p-group = (idx&3)*4) ===
    float a0 = 0.f, a1 = 0.f, a2 = 0.f, a3 = 0.f;
#pragma unroll
    for (int r = 0; r < 8; r++) {
        int idx = r * 512 + t;
        float oh = s_oh[idx >> 2];
        a0 = fmaf(oh, v[r].x, a0);
        a1 = fmaf(oh, v[r].y, a1);
        a2 = fmaf(oh, v[r].z, a2);
        a3 = fmaf(oh, v[r].w, a3);
    }

    // reduce over lanes congruent mod 4 (p-group fixed = (lane&3)*4)
#pragma unroll
    for (int off = 16; off >= 4; off >>= 1) {
        a0 += __shfl_down_sync(0xffffffffu, a0, off);
        a1 += __shfl_down_sync(0xffffffffu, a1, off);
        a2 += __shfl_down_sync(0xffffffffu, a2, off);
        a3 += __shfl_down_sync(0xffffffffu, a3, off);
    }
    int lane = t & 31, wid = t >> 5;
    if (lane < 4) {
        sred[wid * PP + lane * 4 + 0] = a0;
        sred[wid * PP + lane * 4 + 1] = a1;
        sred[wid * PP + lane * 4 + 2] = a2;
        sred[wid * PP + lane * 4 + 3] = a3;
    }
    __syncthreads();
    if (t < PP) {
        float s = 0.0f;
#pragma unroll
        for (int w = 0; w < 16; w++) s += sred[w * PP + t];
        atomicAdd(&q[n * PP + t], s);
    }
}

// ---------------------------------------------------------------------------
extern "C" void kernel_launch(void* const* d_in, const int* in_sizes, int n_in,
                              void* d_out, int out_size) {
    const float* x    = (const float*)d_in[0];      // [256,16]
    const void*  ei   = d_in[1];                    // [2,32768] (int64 cast to int32)
    const float* W    = (const float*)d_in[2];      // [16,2048]
    const float* bias = (const float*)d_in[3];      // [2048]
    const float* Wq   = (const float*)d_in[4];      // [256,2048,16]
    const float* bq   = (const float*)d_in[5];      // [256,16]
    float*       q    = (float*)d_out;              // [256,16]

    k_edges<<<EE / 256, 256>>>(ei, bq, q);
    k_mega<<<2 * NN, 512>>>(x, W, bias, Wq, q);
}